// round 10
// baseline (speedup 1.0000x reference)
#include <cuda_runtime.h>
#include <cuda_bf16.h>
#include <cuda_fp16.h>
#include <math.h>
#include <stdint.h>

#define B_    64
#define D_    512
#define S_    2048
#define K_    8
#define NCAND 16
#define TWO_D 1024

// ---------------- scratch (static device globals) ----------------
__device__ __nv_bfloat16 g_pehi[S_ * TWO_D];   // PE hi [s][e]
__device__ __nv_bfloat16 g_pelo[S_ * TWO_D];   // PE lo [s][e]
__device__ __nv_bfloat16 g_w1h [D_ * TWO_D];   // W1 hi [d][e] full
__device__ __nv_bfloat16 g_w1lo[D_ * TWO_D];   // W1 lo [d][e] full
__device__ __half        g_w1f [D_ * D_];      // W1[:, :512] fp16 [d][e]
__device__ float g_w1t [D_ * D_];              // W1[:, :512] fp32 [e][d]
__device__ float g_p1  [S_ * D_];              // PE@W1^T + b1 [s][d]
__device__ float g_mpart[(S_ / 32) * B_ * D_]; // mean partials [tile][b*D+d]
__device__ float g_gb  [B_ * D_];
__device__ float g_score[B_ * S_];

// ---------------- PTX helpers ----------------
__device__ __forceinline__ uint32_t smem_u32(const void* p) {
    return (uint32_t)__cvta_generic_to_shared(p);
}
__device__ __forceinline__ uint32_t h2u(__half2 h) {
    union { __half2 h; uint32_t u; } cvt;
    cvt.h = h;
    return cvt.u;
}
__device__ __forceinline__ void cp16(uint32_t dst, const void* src) {
    asm volatile("cp.async.cg.shared.global [%0], [%1], 16;" :: "r"(dst), "l"(src));
}
#define CP_COMMIT() asm volatile("cp.async.commit_group;" ::: "memory")
#define CP_WAIT(n)  asm volatile("cp.async.wait_group %0;" :: "n"(n) : "memory")

__device__ __forceinline__ void ldsm4(uint32_t* r, uint32_t a) {
    asm volatile("ldmatrix.sync.aligned.m8n8.x4.shared.b16 {%0,%1,%2,%3}, [%4];"
        : "=r"(r[0]), "=r"(r[1]), "=r"(r[2]), "=r"(r[3]) : "r"(a));
}
__device__ __forceinline__ void ldsm4t(uint32_t* r, uint32_t a) {
    asm volatile("ldmatrix.sync.aligned.m8n8.x4.trans.shared.b16 {%0,%1,%2,%3}, [%4];"
        : "=r"(r[0]), "=r"(r[1]), "=r"(r[2]), "=r"(r[3]) : "r"(a));
}
__device__ __forceinline__ void ldsm2(uint32_t* r, uint32_t a) {
    asm volatile("ldmatrix.sync.aligned.m8n8.x2.shared.b16 {%0,%1}, [%2];"
        : "=r"(r[0]), "=r"(r[1]) : "r"(a));
}
__device__ __forceinline__ void mma_bf_f32(float* c, const uint32_t* a, const uint32_t* b) {
    asm volatile(
        "mma.sync.aligned.m16n8k16.row.col.f32.bf16.bf16.f32 "
        "{%0,%1,%2,%3}, {%4,%5,%6,%7}, {%8,%9}, {%0,%1,%2,%3};"
        : "+f"(c[0]), "+f"(c[1]), "+f"(c[2]), "+f"(c[3])
        : "r"(a[0]), "r"(a[1]), "r"(a[2]), "r"(a[3]), "r"(b[0]), "r"(b[1]));
}
__device__ __forceinline__ void mma_h_h(uint32_t* c, const uint32_t* a, const uint32_t* b) {
    asm volatile(
        "mma.sync.aligned.m16n8k16.row.col.f16.f16.f16.f16 "
        "{%0,%1}, {%2,%3,%4,%5}, {%6,%7}, {%0,%1};"
        : "+r"(c[0]), "+r"(c[1])
        : "r"(a[0]), "r"(a[1]), "r"(a[2]), "r"(a[3]), "r"(b[0]), "r"(b[1]));
}

// ---------------------------------------------------------------
// 1) transpose (32x32): x[b][d][s] -> out_feat[b][s][d] + mean partials
// ---------------------------------------------------------------
__global__ void transpose_fused_kernel(const float* __restrict__ x,
                                       float* __restrict__ out_feat) {
    __shared__ float tile[32][33];
    int b  = blockIdx.z;
    int d0 = blockIdx.y * 32;
    int s0 = blockIdx.x * 32;
    const float* xb = x + (size_t)b * D_ * S_;
    #pragma unroll
    for (int r = 0; r < 32; r += 8)
        tile[threadIdx.y + r][threadIdx.x] =
            xb[(size_t)(d0 + threadIdx.y + r) * S_ + s0 + threadIdx.x];
    __syncthreads();
    float* ob = out_feat + (size_t)b * S_ * D_;
    #pragma unroll
    for (int r = 0; r < 32; r += 8) {
        int s = s0 + threadIdx.y + r;
        ob[(size_t)s * D_ + d0 + threadIdx.x] = tile[threadIdx.x][threadIdx.y + r];
    }
    if (threadIdx.y == 0) {
        float sum = 0.f;
        #pragma unroll
        for (int sl = 0; sl < 32; sl++) sum += tile[threadIdx.x][sl];
        g_mpart[(size_t)blockIdx.x * (B_ * D_) + b * D_ + d0 + threadIdx.x] = sum;
    }
}

// ---------------------------------------------------------------
// 2) PE (hi/lo bf16) + W1 conversions
// ---------------------------------------------------------------
__global__ void pew1_kernel(const float* __restrict__ W1) {
    int bx = blockIdx.x;
    if (bx < S_) {
        int s = bx, i = threadIdx.x;
        float div = expf(-(float)(2 * i) * (logf(10000.0f) / (float)TWO_D));
        float sv, cv;
        sincosf((float)s * div, &sv, &cv);
        __nv_bfloat16 hs = __float2bfloat16_rn(sv);
        __nv_bfloat16 hc = __float2bfloat16_rn(cv);
        __nv_bfloat16 ls = __float2bfloat16_rn(sv - __bfloat162float(hs));
        __nv_bfloat16 lc = __float2bfloat16_rn(cv - __bfloat162float(hc));
        ((__nv_bfloat162*)g_pehi)[(size_t)s * (TWO_D / 2) + i] =
            __nv_bfloat162(hs, hc);
        ((__nv_bfloat162*)g_pelo)[(size_t)s * (TWO_D / 2) + i] =
            __nv_bfloat162(ls, lc);
    } else {
        int idx = (bx - S_) * 512 + threadIdx.x;
        int d = idx >> 10, e = idx & 1023;
        float v = W1[idx];
        __nv_bfloat16 h = __float2bfloat16_rn(v);
        g_w1h[idx]  = h;
        g_w1lo[idx] = __float2bfloat16_rn(v - __bfloat162float(h));
        if (e < 512) {
            g_w1f[d * 512 + e] = __float2half_rn(v);
            g_w1t[(size_t)e * D_ + d] = v;
        }
    }
}

// ---------------------------------------------------------------
// 3) p1 (hi/lo bf16 MMA, 64x64 tiles; grid y<8) + meang (grid y==8)
// ---------------------------------------------------------------
#define P1_SMEM (2 * 32768)

__global__ void __launch_bounds__(256, 1)
p1meang_kernel(const float* __restrict__ b1, const float* __restrict__ W1) {
    int tid = threadIdx.x;
    if (blockIdx.y == 8) {
        // --- meang: 2 b's per block ---
        __shared__ float sm[D_];
        #pragma unroll
        for (int bb = 0; bb < 2; bb++) {
            int b = blockIdx.x * 2 + bb;
            for (int dd = tid; dd < D_; dd += 256) {
                float s = 0.f;
                #pragma unroll
                for (int t = 0; t < S_ / 32; t++)
                    s += g_mpart[(size_t)t * (B_ * D_) + b * D_ + dd];
                sm[dd] = s * (1.0f / S_);
            }
            __syncthreads();
            for (int dd = tid; dd < D_; dd += 256) {
                const float4* w = (const float4*)(W1 + (size_t)dd * TWO_D + D_);
                float acc = 0.f;
                #pragma unroll 8
                for (int e4 = 0; e4 < D_ / 4; e4++) {
                    float4 v = w[e4];
                    acc = fmaf(sm[4 * e4 + 0], v.x, acc);
                    acc = fmaf(sm[4 * e4 + 1], v.y, acc);
                    acc = fmaf(sm[4 * e4 + 2], v.z, acc);
                    acc = fmaf(sm[4 * e4 + 3], v.w, acc);
                }
                g_gb[b * D_ + dd] = acc;
            }
            __syncthreads();
        }
        return;
    }

    extern __shared__ char dsm[];
    uint32_t smb = smem_u32(dsm);
    int lane = tid & 31, w = tid >> 5;
    int wm = w & 1, wn = w >> 1;
    int quad = lane >> 2, qd = lane & 3;
    int s0 = blockIdx.x * 64;
    int d0b = blockIdx.y * 64;

    const char* Ah = (const char*)g_pehi + (size_t)s0 * 2048;
    const char* Al = (const char*)g_pelo + (size_t)s0 * 2048;
    const char* Bh = (const char*)g_w1h + (size_t)d0b * 2048;
    const char* Bl = (const char*)g_w1lo + (size_t)d0b * 2048;

    #define P1_PF(t) do { \
        uint32_t base_ = smb + ((t) & 1) * 32768; \
        _Pragma("unroll") \
        for (int q = 0; q < 2; q++) { \
            int idx = tid + q * 256; \
            int row = idx >> 3, c = idx & 7; \
            uint32_t off = row * 128 + (((c ^ (row & 7))) << 4); \
            size_t src = (size_t)row * 2048 + (size_t)(t) * 128 + c * 16; \
            cp16(base_ + off,          Ah + src); \
            cp16(base_ + 8192 + off,   Al + src); \
            cp16(base_ + 16384 + off,  Bh + src); \
            cp16(base_ + 24576 + off,  Bl + src); \
        } \
        CP_COMMIT(); \
    } while (0)

    P1_PF(0);
    P1_PF(1);

    float C[2][2][4];
    #pragma unroll
    for (int i = 0; i < 2; i++)
        #pragma unroll
        for (int j = 0; j < 2; j++)
            #pragma unroll
            for (int k = 0; k < 4; k++) C[i][j][k] = 0.f;

    for (int t = 0; t < 16; ++t) {
        if (t >= 14) { CP_WAIT(0); } else { CP_WAIT(1); }
        __syncthreads();
        uint32_t bA = smb + (t & 1) * 32768;
        #pragma unroll
        for (int kk = 0; kk < 4; kk++) {
            uint32_t ah[2][4], al[2][4];
            #pragma unroll
            for (int i = 0; i < 2; i++) {
                int r = wm * 32 + i * 16 + (lane & 15);
                uint32_t ch = (uint32_t)((kk << 1) | (lane >> 4));
                uint32_t off = r * 128 + ((ch ^ (uint32_t)(r & 7)) << 4);
                ldsm4(ah[i], bA + off);
                ldsm4(al[i], bA + 8192 + off);
            }
            uint32_t bh[2][2], bl[2][2];
            #pragma unroll
            for (int j = 0; j < 2; j++) {
                int rn = wn * 16 + j * 8 + (lane & 7);
                uint32_t ch = (uint32_t)((kk << 1) | ((lane >> 3) & 1));
                uint32_t off = rn * 128 + ((ch ^ (uint32_t)(rn & 7)) << 4);
                ldsm2(bh[j], bA + 16384 + off);
                ldsm2(bl[j], bA + 24576 + off);
            }
            #pragma unroll
            for (int i = 0; i < 2; i++)
                #pragma unroll
                for (int j = 0; j < 2; j++) {
                    mma_bf_f32(C[i][j], ah[i], bh[j]);
                    mma_bf_f32(C[i][j], ah[i], bl[j]);
                    mma_bf_f32(C[i][j], al[i], bh[j]);
                }
        }
        __syncthreads();
        if (t + 2 < 16) P1_PF(t + 2);
    }

    #pragma unroll
    for (int i = 0; i < 2; i++) {
        int sg = s0 + wm * 32 + i * 16 + quad;
        #pragma unroll
        for (int j = 0; j < 2; j++) {
            int d = d0b + wn * 16 + j * 8 + qd * 2;
            float2 bv = *(const float2*)(b1 + d);
            *(float2*)(g_p1 + (size_t)sg * D_ + d) =
                make_float2(C[i][j][0] + bv.x, C[i][j][1] + bv.y);
            *(float2*)(g_p1 + (size_t)(sg + 8) * D_ + d) =
                make_float2(C[i][j][2] + bv.x, C[i][j][3] + bv.y);
        }
    }
    #undef P1_PF
}

// ---------------------------------------------------------------
// 4) MAIN v4: fp16 mma (f16 accum), s-tile 64, nb-inner, precomputed
//    swizzle addresses + ldsm4 B loads.
// ---------------------------------------------------------------
#define SMEM_A   (2 * 4096)
#define SMEM_Boff SMEM_A
#define SMEM_DYN (SMEM_A + 2 * 32768)  // 72KB -> 2 CTAs/SM

__global__ void __launch_bounds__(256, 2)
fused_mma_kernel(const float* __restrict__ x, const float* __restrict__ W2,
                 const float* __restrict__ b2)
{
    extern __shared__ char dsm[];
    __shared__ float sW2[D_];
    __shared__ float sG[D_];
    __shared__ float sred[4][64];

    const uint32_t smA = smem_u32(dsm);
    const uint32_t smB = smA + SMEM_Boff;

    int tid = threadIdx.x;
    int lane = tid & 31;
    int w = tid >> 5;
    int wm = w & 1, wn = w >> 1;
    int quad = lane >> 2, qd = lane & 3;
    int b = blockIdx.y;
    int s0 = blockIdx.x * 64;

    for (int i = tid; i < D_; i += 256) {
        sW2[i] = W2[i];
        sG[i]  = g_gb[b * D_ + i];
    }

    const float* xA = x + (size_t)b * D_ * S_ + s0;

    uint32_t bbase[8];
    #pragma unroll
    for (int pq = 0; pq < 8; pq++) {
        int jj = 2 * pq + ((lane >> 4) & 1);
        int rn = (jj >> 2) * 128 + wn * 32 + (jj & 3) * 8 + (lane & 7);
        bbase[pq] = (uint32_t)(rn * 64 + (((rn >> 1) & 3) << 4));
    }
    uint32_t aoff[2];
    {
        int row0 = ((lane >> 4) << 3) + (lane & 7);
        #pragma unroll
        for (int i = 0; i < 2; i++) {
            int col16 = ((wm * 32 + i * 16) >> 3) + ((lane >> 3) & 1);
            aoff[i] = (uint32_t)(row0 * 128 + ((col16 ^ (row0 & 7)) << 4));
        }
    }
    const uint32_t chlane = ((lane >> 3) & 1) << 4;

    #define B_PF(tc) do { \
        _Pragma("unroll") \
        for (int q = 0; q < 8; q++) { \
            int idx = tid + q * 256; \
            int row = idx >> 2, c = idx & 3; \
            uint32_t dst = smB + ((tc) & 1) * 32768 + row * 64 + \
                           (((uint32_t)(c ^ ((row >> 1) & 3))) << 4); \
            cp16(dst, (const char*)g_w1f + row * 1024 + (tc) * 64 + c * 16); \
        } \
        CP_COMMIT(); \
    } while (0)

    float4 st[2];
    #define A_LDG(kc) do { \
        _Pragma("unroll") \
        for (int q = 0; q < 2; q++) { \
            int idx = tid + q * 256; \
            int e = (kc) * 32 + (idx >> 4), c4 = idx & 15; \
            st[q] = __ldg((const float4*)(xA + (size_t)e * S_ + c4 * 4)); \
        } \
    } while (0)
    #define A_STS(kc) do { \
        _Pragma("unroll") \
        for (int q = 0; q < 2; q++) { \
            int idx = tid + q * 256; \
            int el = idx >> 4, c4 = idx & 15; \
            __half2 h01 = __floats2half2_rn(st[q].x, st[q].y); \
            __half2 h23 = __floats2half2_rn(st[q].z, st[q].w); \
            uint32_t off = (uint32_t)(((kc) & 1) * 4096 + el * 128 + \
                ((((c4 >> 1)) ^ (el & 7)) << 4) + (c4 & 1) * 8); \
            *(uint2*)(dsm + off) = make_uint2(h2u(h01), h2u(h23)); \
        } \
    } while (0)

    uint32_t C[2][16][2];
    #pragma unroll
    for (int i = 0; i < 2; i++)
        #pragma unroll
        for (int j = 0; j < 16; j++) { C[i][j][0] = 0u; C[i][j][1] = 0u; }

    B_PF(0);
    A_LDG(0);
    A_STS(0);

    for (int t = 0; t < 16; ++t) {
        if (t < 15) A_LDG(t + 1);
        CP_WAIT(0);
        __syncthreads();
        if (t < 15) B_PF(t + 1);

        uint32_t Abase = smA + (t & 1) * 4096;
        uint32_t Bbase = smB + (t & 1) * 32768;
        #pragma unroll
        for (int kk = 0; kk < 2; kk++) {
            uint32_t a[2][4];
            ldsm4t(a[0], Abase + kk * 2048 + aoff[0]);
            ldsm4t(a[1], Abase + kk * 2048 + aoff[1]);
            uint32_t chx = chlane ^ ((uint32_t)kk << 5);
            #pragma unroll
            for (int pq = 0; pq < 8; pq++) {
                uint32_t bf[4];
                ldsm4(bf, Bbase + (bbase[pq] ^ chx));
                mma_h_h(C[0][2 * pq],     a[0], bf);
                mma_h_h(C[1][2 * pq],     a[1], bf);
                mma_h_h(C[0][2 * pq + 1], a[0], bf + 2);
                mma_h_h(C[1][2 * pq + 1], a[1], bf + 2);
            }
        }
        if (t < 15) A_STS(t + 1);
    }
    #undef B_PF
    #undef A_LDG
    #undef A_STS

    float acc[2][2] = {{0.f, 0.f}, {0.f, 0.f}};
    #pragma unroll
    for (int i = 0; i < 2; i++) {
        int r0 = wm * 32 + i * 16 + quad;
        #pragma unroll
        for (int j2 = 0; j2 < 16; j2++) {
            int d = (j2 >> 2) * 128 + wn * 32 + (j2 & 3) * 8 + qd * 2;
            float w2x = sW2[d], w2y = sW2[d + 1];
            float gx = sG[d],  gy = sG[d + 1];
            const float* p = g_p1 + (size_t)(s0 + r0) * D_ + d;
            float2 pA = *(const float2*)p;
            float2 pB = *(const float2*)(p + 8 * D_);
            __half2 ha = *(__half2*)&C[i][j2][0];
            __half2 hb = *(__half2*)&C[i][j2][1];
            float v0 = fmaxf(__low2float(ha)  + pA.x + gx, 0.f);
            float v1 = fmaxf(__high2float(ha) + pA.y + gy, 0.f);
            float v2 = fmaxf(__low2float(hb)  + pB.x + gx, 0.f);
            float v3 = fmaxf(__high2float(hb) + pB.y + gy, 0.f);
            acc[i][0] = fmaf(v0, w2x, fmaf(v1, w2y, acc[i][0]));
            acc[i][1] = fmaf(v2, w2x, fmaf(v3, w2y, acc[i][1]));
        }
    }

    #pragma unroll
    for (int i = 0; i < 2; i++)
        #pragma unroll
        for (int m = 0; m < 2; m++) {
            float v = acc[i][m];
            v += __shfl_xor_sync(0xffffffffu, v, 1);
            v += __shfl_xor_sync(0xffffffffu, v, 2);
            if (qd == 0) sred[wn][wm * 32 + i * 16 + m * 8 + quad] = v;
        }
    __syncthreads();
    if (tid < 64)
        g_score[(size_t)b * S_ + s0 + tid] =
            sred[0][tid] + sred[1][tid] + sred[2][tid] + sred[3][tid] + b2[0];
}

// ---------------------------------------------------------------
// 5) MERGED select: top-16 approx -> exact rescore -> top-8 ->
//    scatter ones + gather selected features from smem xcol.
//    grid = B_, 512 threads.
// ---------------------------------------------------------------
__global__ void __launch_bounds__(512)
select_kernel(const float* __restrict__ x, const float* __restrict__ W2,
              float* __restrict__ out_idx, float* __restrict__ out_sel)
{
    __shared__ float xcol[NCAND][D_];
    __shared__ float cval[256];
    __shared__ int   cidx[256];
    __shared__ int   scand[NCAND];
    __shared__ float wsum[16][NCAND];
    __shared__ float cscore[NCAND];
    __shared__ int   chosen_s[K_];
    __shared__ int   cslot_s[K_];

    int b = blockIdx.x, tid = threadIdx.x;
    int w = tid >> 5, lane = tid & 31;
    const float* sc = g_score + (size_t)b * S_;

    // --- phase 1: per-warp top-16 of its 128 scores ---
    float v[4];
    #pragma unroll
    for (int k = 0; k < 4; k++) v[k] = sc[w * 128 + k * 32 + lane];
    for (int it = 0; it < NCAND; it++) {
        float lv = v[0]; int lk = 0;
        #pragma unroll
        for (int k = 1; k < 4; k++)
            if (v[k] > lv) { lv = v[k]; lk = k; }
        int gidx = w * 128 + lk * 32 + lane;
        float bv = lv; int bi = gidx;
        #pragma unroll
        for (int off = 16; off > 0; off >>= 1) {
            float ov = __shfl_xor_sync(0xffffffffu, bv, off);
            int   oi = __shfl_xor_sync(0xffffffffu, bi, off);
            if (ov > bv || (ov == bv && oi < bi)) { bv = ov; bi = oi; }
        }
        if (gidx == bi) v[lk] = -INFINITY;
        if (lane == 0) { cval[w * 16 + it] = bv; cidx[w * 16 + it] = bi; }
    }
    __syncthreads();
    // --- phase 1b: warp 0 merges 256 candidates ---
    if (w == 0) {
        float v2[8]; int i2[8];
        #pragma unroll
        for (int k = 0; k < 8; k++) {
            v2[k] = cval[k * 32 + lane];
            i2[k] = cidx[k * 32 + lane];
        }
        for (int it = 0; it < NCAND; it++) {
            float lv = v2[0]; int lk = 0;
            #pragma unroll
            for (int k = 1; k < 8; k++)
                if (v2[k] > lv || (v2[k] == lv && i2[k] < i2[lk])) { lv = v2[k]; lk = k; }
            float bv = lv; int bi = i2[lk];
            #pragma unroll
            for (int off = 16; off > 0; off >>= 1) {
                float ov = __shfl_xor_sync(0xffffffffu, bv, off);
                int   oi = __shfl_xor_sync(0xffffffffu, bi, off);
                if (ov > bv || (ov == bv && oi < bi)) { bv = ov; bi = oi; }
            }
            if (i2[lk] == bi) v2[lk] = -INFINITY;
            if (lane == 0) scand[it] = bi;
        }
    }
    __syncthreads();

    // --- phase 2: load x columns of the 16 candidates ---
    for (int idx = tid; idx < NCAND * D_; idx += 512) {
        int c = idx >> 9, e = idx & 511;
        xcol[c][e] = x[((size_t)b * D_ + e) * S_ + scand[c]];
    }
    __syncthreads();

    // --- phase 3: exact fp32 rescore; d = tid covers all of D ---
    int d = tid;
    float accv[NCAND];
    #pragma unroll
    for (int c = 0; c < NCAND; c++) accv[c] = 0.f;
    const float* wt = g_w1t + d;
    for (int e = 0; e < D_; e++) {
        float wv = wt[(size_t)e * D_];
        #pragma unroll
        for (int c = 0; c < NCAND; c++)
            accv[c] = fmaf(wv, xcol[c][e], accv[c]);
    }
    float w2v = W2[d];
    float gv  = g_gb[b * D_ + d];
    #pragma unroll
    for (int c = 0; c < NCAND; c++) {
        float hv = accv[c] + g_p1[(size_t)scand[c] * D_ + d] + gv;
        hv = fmaxf(hv, 0.f);
        float part = hv * w2v;
        #pragma unroll
        for (int off = 16; off > 0; off >>= 1)
            part += __shfl_xor_sync(0xffffffffu, part, off);
        if (lane == 0) wsum[w][c] = part;
    }
    __syncthreads();
    if (tid < NCAND) {
        float s = 0.f;
        #pragma unroll
        for (int q = 0; q < 16; q++) s += wsum[q][tid];
        cscore[tid] = s;
    }
    __syncthreads();

    // --- phase 4: thread 0 exact top-8, ascending sort with slot map ---
    if (tid == 0) {
        bool used[NCAND];
        #pragma unroll
        for (int c = 0; c < NCAND; c++) used[c] = false;
        int ch[K_], sl[K_];
        for (int k = 0; k < K_; k++) {
            float best = -INFINITY; int bi = S_, bc = -1;
            for (int c = 0; c < NCAND; c++) {
                if (used[c]) continue;
                if (cscore[c] > best || (cscore[c] == best && scand[c] < bi)) {
                    best = cscore[c]; bi = scand[c]; bc = c;
                }
            }
            used[bc] = true;
            ch[k] = bi; sl[k] = bc;
        }
        for (int a = 1; a < K_; a++) {
            int vv = ch[a], ss = sl[a]; int j = a - 1;
            while (j >= 0 && ch[j] > vv) {
                ch[j + 1] = ch[j]; sl[j + 1] = sl[j]; j--;
            }
            ch[j + 1] = vv; sl[j + 1] = ss;
        }
        for (int k = 0; k < K_; k++) { chosen_s[k] = ch[k]; cslot_s[k] = sl[k]; }
    }
    __syncthreads();

    // --- phase 5: outputs ---
    if (tid < K_)
        out_idx[((size_t)b * K_ + tid) * S_ + chosen_s[tid]] = 1.0f;
    #pragma unroll
    for (int k = 0; k < K_; k++)
        out_sel[((size_t)b * K_ + k) * D_ + tid] = xcol[cslot_s[k]][tid];
}

// ---------------------------------------------------------------
// 6) zero indices output
// ---------------------------------------------------------------
__global__ void zero_indices_kernel(float* __restrict__ out) {
    size_t i = (size_t)blockIdx.x * blockDim.x + threadIdx.x;
    ((float4*)out)[i] = make_float4(0.f, 0.f, 0.f, 0.f);
}

// ---------------------------------------------------------------
extern "C" void kernel_launch(void* const* d_in, const int* in_sizes, int n_in,
                              void* d_out, int out_size) {
    const float* x  = (const float*)d_in[0];
    const float* W1 = (const float*)d_in[1];
    const float* b1 = (const float*)d_in[2];
    const float* W2 = (const float*)d_in[3];
    const float* b2 = (const float*)d_in[4];
    float* out = (float*)d_out;

    const size_t IDX_SZ = (size_t)B_ * K_ * S_;
    const size_t SEL_SZ = (size_t)B_ * K_ * D_;
    float* out_idx  = out;
    float* out_sel  = out + IDX_SZ;
    float* out_feat = out + IDX_SZ + SEL_SZ;

    static cudaStream_t s1 = nullptr;
    static cudaEvent_t evFork = nullptr, evJoin = nullptr, evZ = nullptr;
    if (s1 == nullptr) {
        cudaStreamCreateWithFlags(&s1, cudaStreamNonBlocking);
        cudaEventCreateWithFlags(&evFork, cudaEventDisableTiming);
        cudaEventCreateWithFlags(&evJoin, cudaEventDisableTiming);
        cudaEventCreateWithFlags(&evZ, cudaEventDisableTiming);
        cudaFuncSetAttribute(fused_mma_kernel,
                             cudaFuncAttributeMaxDynamicSharedMemorySize, SMEM_DYN);
        cudaFuncSetAttribute(p1meang_kernel,
                             cudaFuncAttributeMaxDynamicSharedMemorySize, P1_SMEM);
    }

    // fork: transpose on s1
    cudaEventRecord(evFork, 0);
    cudaStreamWaitEvent(s1, evFork, 0);
    transpose_fused_kernel<<<dim3(S_ / 32, D_ / 32, B_), dim3(32, 8), 0, s1>>>(x, out_feat); // call 1
    cudaEventRecord(evJoin, s1);

    pew1_kernel<<<S_ + (D_ * TWO_D) / 512, 512>>>(W1);                        // call 2

    cudaStreamWaitEvent(0, evJoin, 0);
    p1meang_kernel<<<dim3(32, 9), 256, P1_SMEM>>>(b1, W1);                    // call 3
    fused_mma_kernel<<<dim3(S_ / 64, B_), 256, SMEM_DYN>>>(x, W2, b2);        // call 4 (profiled)

    zero_indices_kernel<<<(unsigned)(IDX_SZ / 4 / 256), 256, 0, s1>>>(out_idx); // call 5 (s1)
    cudaEventRecord(evZ, s1);
    cudaStreamWaitEvent(0, evZ, 0);
    select_kernel<<<B_, 512>>>(x, W2, out_idx, out_sel);                      // call 6
}

// round 11
// speedup vs baseline: 1.0235x; 1.0235x over previous
#include <cuda_runtime.h>
#include <cuda_bf16.h>
#include <cuda_fp16.h>
#include <math.h>
#include <stdint.h>

#define B_    64
#define D_    512
#define S_    2048
#define K_    8
#define NCAND 16
#define TWO_D 1024

// ---------------- scratch (static device globals) ----------------
__device__ __nv_bfloat16 g_pehi[S_ * TWO_D];   // PE hi [s][e]
__device__ __nv_bfloat16 g_pelo[S_ * TWO_D];   // PE lo [s][e]
__device__ __nv_bfloat16 g_w1h [D_ * TWO_D];   // W1 hi [d][e] full
__device__ __nv_bfloat16 g_w1lo[D_ * TWO_D];   // W1 lo [d][e] full
__device__ __half        g_w1f [D_ * D_];      // W1[:, :512] fp16 [d][e]
__device__ float g_w1t [D_ * D_];              // W1[:, :512] fp32 [e][d]
__device__ float g_p1  [S_ * D_];              // PE@W1^T + b1 [s][d]
__device__ float g_mpart[(S_ / 32) * B_ * D_]; // mean partials [tile][b*D+d]
__device__ float g_gb  [B_ * D_];
__device__ float g_score[B_ * S_];

// ---------------- PTX helpers ----------------
__device__ __forceinline__ uint32_t smem_u32(const void* p) {
    return (uint32_t)__cvta_generic_to_shared(p);
}
__device__ __forceinline__ uint32_t h2u(__half2 h) {
    union { __half2 h; uint32_t u; } cvt;
    cvt.h = h;
    return cvt.u;
}
__device__ __forceinline__ void cp16(uint32_t dst, const void* src) {
    asm volatile("cp.async.cg.shared.global [%0], [%1], 16;" :: "r"(dst), "l"(src));
}
#define CP_COMMIT() asm volatile("cp.async.commit_group;" ::: "memory")
#define CP_WAIT(n)  asm volatile("cp.async.wait_group %0;" :: "n"(n) : "memory")

__device__ __forceinline__ void ldsm4(uint32_t* r, uint32_t a) {
    asm volatile("ldmatrix.sync.aligned.m8n8.x4.shared.b16 {%0,%1,%2,%3}, [%4];"
        : "=r"(r[0]), "=r"(r[1]), "=r"(r[2]), "=r"(r[3]) : "r"(a));
}
__device__ __forceinline__ void ldsm4t(uint32_t* r, uint32_t a) {
    asm volatile("ldmatrix.sync.aligned.m8n8.x4.trans.shared.b16 {%0,%1,%2,%3}, [%4];"
        : "=r"(r[0]), "=r"(r[1]), "=r"(r[2]), "=r"(r[3]) : "r"(a));
}
__device__ __forceinline__ void ldsm2(uint32_t* r, uint32_t a) {
    asm volatile("ldmatrix.sync.aligned.m8n8.x2.shared.b16 {%0,%1}, [%2];"
        : "=r"(r[0]), "=r"(r[1]) : "r"(a));
}
__device__ __forceinline__ void mma_bf_f32(float* c, const uint32_t* a, const uint32_t* b) {
    asm volatile(
        "mma.sync.aligned.m16n8k16.row.col.f32.bf16.bf16.f32 "
        "{%0,%1,%2,%3}, {%4,%5,%6,%7}, {%8,%9}, {%0,%1,%2,%3};"
        : "+f"(c[0]), "+f"(c[1]), "+f"(c[2]), "+f"(c[3])
        : "r"(a[0]), "r"(a[1]), "r"(a[2]), "r"(a[3]), "r"(b[0]), "r"(b[1]));
}
__device__ __forceinline__ void mma_h_h(uint32_t* c, const uint32_t* a, const uint32_t* b) {
    asm volatile(
        "mma.sync.aligned.m16n8k16.row.col.f16.f16.f16.f16 "
        "{%0,%1}, {%2,%3,%4,%5}, {%6,%7}, {%0,%1};"
        : "+r"(c[0]), "+r"(c[1])
        : "r"(a[0]), "r"(a[1]), "r"(a[2]), "r"(a[3]), "r"(b[0]), "r"(b[1]));
}

// ---------------------------------------------------------------
// 1) transpose (32x32): x[b][d][s] -> out_feat[b][s][d] + mean partials
// ---------------------------------------------------------------
__global__ void transpose_fused_kernel(const float* __restrict__ x,
                                       float* __restrict__ out_feat) {
    __shared__ float tile[32][33];
    int b  = blockIdx.z;
    int d0 = blockIdx.y * 32;
    int s0 = blockIdx.x * 32;
    const float* xb = x + (size_t)b * D_ * S_;
    #pragma unroll
    for (int r = 0; r < 32; r += 8)
        tile[threadIdx.y + r][threadIdx.x] =
            xb[(size_t)(d0 + threadIdx.y + r) * S_ + s0 + threadIdx.x];
    __syncthreads();
    float* ob = out_feat + (size_t)b * S_ * D_;
    #pragma unroll
    for (int r = 0; r < 32; r += 8) {
        int s = s0 + threadIdx.y + r;
        ob[(size_t)s * D_ + d0 + threadIdx.x] = tile[threadIdx.x][threadIdx.y + r];
    }
    if (threadIdx.y == 0) {
        float sum = 0.f;
        #pragma unroll
        for (int sl = 0; sl < 32; sl++) sum += tile[threadIdx.x][sl];
        g_mpart[(size_t)blockIdx.x * (B_ * D_) + b * D_ + d0 + threadIdx.x] = sum;
    }
}

// ---------------------------------------------------------------
// 2) PE (hi/lo bf16) + W1 conversions
// ---------------------------------------------------------------
__global__ void pew1_kernel(const float* __restrict__ W1) {
    int bx = blockIdx.x;
    if (bx < S_) {
        int s = bx, i = threadIdx.x;
        float div = expf(-(float)(2 * i) * (logf(10000.0f) / (float)TWO_D));
        float sv, cv;
        sincosf((float)s * div, &sv, &cv);
        __nv_bfloat16 hs = __float2bfloat16_rn(sv);
        __nv_bfloat16 hc = __float2bfloat16_rn(cv);
        __nv_bfloat16 ls = __float2bfloat16_rn(sv - __bfloat162float(hs));
        __nv_bfloat16 lc = __float2bfloat16_rn(cv - __bfloat162float(hc));
        ((__nv_bfloat162*)g_pehi)[(size_t)s * (TWO_D / 2) + i] =
            __nv_bfloat162(hs, hc);
        ((__nv_bfloat162*)g_pelo)[(size_t)s * (TWO_D / 2) + i] =
            __nv_bfloat162(ls, lc);
    } else {
        int idx = (bx - S_) * 512 + threadIdx.x;
        int d = idx >> 10, e = idx & 1023;
        float v = W1[idx];
        __nv_bfloat16 h = __float2bfloat16_rn(v);
        g_w1h[idx]  = h;
        g_w1lo[idx] = __float2bfloat16_rn(v - __bfloat162float(h));
        if (e < 512) {
            g_w1f[d * 512 + e] = __float2half_rn(v);
            g_w1t[(size_t)e * D_ + d] = v;
        }
    }
}

// ---------------------------------------------------------------
// 3) meang: mean combine + g = mean . W1[:,512:]
// ---------------------------------------------------------------
__global__ void meang_kernel(const float* __restrict__ W1) {
    __shared__ float sm[D_];
    int b = blockIdx.x, d = threadIdx.x;
    float s = 0.f;
    #pragma unroll
    for (int t = 0; t < S_ / 32; t++)
        s += g_mpart[(size_t)t * (B_ * D_) + b * D_ + d];
    sm[d] = s * (1.0f / S_);
    __syncthreads();
    const float4* w = (const float4*)(W1 + (size_t)d * TWO_D + D_);
    float acc = 0.f;
    #pragma unroll 8
    for (int e4 = 0; e4 < D_ / 4; e4++) {
        float4 v = w[e4];
        acc = fmaf(sm[4 * e4 + 0], v.x, acc);
        acc = fmaf(sm[4 * e4 + 1], v.y, acc);
        acc = fmaf(sm[4 * e4 + 2], v.z, acc);
        acc = fmaf(sm[4 * e4 + 3], v.w, acc);
    }
    g_gb[b * D_ + d] = acc;
}

// ---------------------------------------------------------------
// 4) p1 via hi/lo bf16 MMA, 64x64 tiles -> 256 CTAs
// ---------------------------------------------------------------
#define P1_SMEM (2 * 32768)

__global__ void __launch_bounds__(256, 1)
p1_mma_kernel(const float* __restrict__ b1) {
    extern __shared__ char dsm[];
    uint32_t smb = smem_u32(dsm);
    int tid = threadIdx.x, lane = tid & 31, w = tid >> 5;
    int wm = w & 1, wn = w >> 1;
    int quad = lane >> 2, qd = lane & 3;
    int s0 = blockIdx.x * 64;
    int d0b = blockIdx.y * 64;

    const char* Ah = (const char*)g_pehi + (size_t)s0 * 2048;
    const char* Al = (const char*)g_pelo + (size_t)s0 * 2048;
    const char* Bh = (const char*)g_w1h + (size_t)d0b * 2048;
    const char* Bl = (const char*)g_w1lo + (size_t)d0b * 2048;

    #define P1_PF(t) do { \
        uint32_t base_ = smb + ((t) & 1) * 32768; \
        _Pragma("unroll") \
        for (int q = 0; q < 2; q++) { \
            int idx = tid + q * 256; \
            int row = idx >> 3, c = idx & 7; \
            uint32_t off = row * 128 + (((c ^ (row & 7))) << 4); \
            size_t src = (size_t)row * 2048 + (size_t)(t) * 128 + c * 16; \
            cp16(base_ + off,          Ah + src); \
            cp16(base_ + 8192 + off,   Al + src); \
            cp16(base_ + 16384 + off,  Bh + src); \
            cp16(base_ + 24576 + off,  Bl + src); \
        } \
        CP_COMMIT(); \
    } while (0)

    P1_PF(0);
    P1_PF(1);

    float C[2][2][4];
    #pragma unroll
    for (int i = 0; i < 2; i++)
        #pragma unroll
        for (int j = 0; j < 2; j++)
            #pragma unroll
            for (int k = 0; k < 4; k++) C[i][j][k] = 0.f;

    for (int t = 0; t < 16; ++t) {
        if (t >= 14) { CP_WAIT(0); } else { CP_WAIT(1); }
        __syncthreads();
        uint32_t bA = smb + (t & 1) * 32768;
        #pragma unroll
        for (int kk = 0; kk < 4; kk++) {
            uint32_t ah[2][4], al[2][4];
            #pragma unroll
            for (int i = 0; i < 2; i++) {
                int r = wm * 32 + i * 16 + (lane & 15);
                uint32_t ch = (uint32_t)((kk << 1) | (lane >> 4));
                uint32_t off = r * 128 + ((ch ^ (uint32_t)(r & 7)) << 4);
                ldsm4(ah[i], bA + off);
                ldsm4(al[i], bA + 8192 + off);
            }
            uint32_t bh[2][2], bl[2][2];
            #pragma unroll
            for (int j = 0; j < 2; j++) {
                int rn = wn * 16 + j * 8 + (lane & 7);
                uint32_t ch = (uint32_t)((kk << 1) | ((lane >> 3) & 1));
                uint32_t off = rn * 128 + ((ch ^ (uint32_t)(rn & 7)) << 4);
                ldsm2(bh[j], bA + 16384 + off);
                ldsm2(bl[j], bA + 24576 + off);
            }
            #pragma unroll
            for (int i = 0; i < 2; i++)
                #pragma unroll
                for (int j = 0; j < 2; j++) {
                    mma_bf_f32(C[i][j], ah[i], bh[j]);
                    mma_bf_f32(C[i][j], ah[i], bl[j]);
                    mma_bf_f32(C[i][j], al[i], bh[j]);
                }
        }
        __syncthreads();
        if (t + 2 < 16) P1_PF(t + 2);
    }

    #pragma unroll
    for (int i = 0; i < 2; i++) {
        int sg = s0 + wm * 32 + i * 16 + quad;
        #pragma unroll
        for (int j = 0; j < 2; j++) {
            int d = d0b + wn * 16 + j * 8 + qd * 2;
            float2 bv = *(const float2*)(b1 + d);
            *(float2*)(g_p1 + (size_t)sg * D_ + d) =
                make_float2(C[i][j][0] + bv.x, C[i][j][1] + bv.y);
            *(float2*)(g_p1 + (size_t)(sg + 8) * D_ + d) =
                make_float2(C[i][j][2] + bv.x, C[i][j][3] + bv.y);
        }
    }
    #undef P1_PF
}

// ---------------------------------------------------------------
// 5) MAIN v5: fp16 mma (f16 accum), s-tile 64, nb-inner,
//    3-stage B pipeline (CP_WAIT(1) slack), 1 sync per k-chunk.
// ---------------------------------------------------------------
#define SMEM_A    (2 * 4096)
#define SMEM_Boff SMEM_A
#define SMEM_DYN  (SMEM_A + 3 * 32768)  // 104KB -> 2 CTAs/SM

__global__ void __launch_bounds__(256, 2)
fused_mma_kernel(const float* __restrict__ x, const float* __restrict__ W2,
                 const float* __restrict__ b2)
{
    extern __shared__ char dsm[];
    __shared__ float sW2[D_];
    __shared__ float sG[D_];
    __shared__ float sred[4][64];

    const uint32_t smA = smem_u32(dsm);
    const uint32_t smB = smA + SMEM_Boff;

    int tid = threadIdx.x;
    int lane = tid & 31;
    int w = tid >> 5;
    int wm = w & 1, wn = w >> 1;
    int quad = lane >> 2, qd = lane & 3;
    int b = blockIdx.y;
    int s0 = blockIdx.x * 64;

    for (int i = tid; i < D_; i += 256) {
        sW2[i] = W2[i];
        sG[i]  = g_gb[b * D_ + i];
    }

    const float* xA = x + (size_t)b * D_ * S_ + s0;

    uint32_t bbase[8];
    #pragma unroll
    for (int pq = 0; pq < 8; pq++) {
        int jj = 2 * pq + ((lane >> 4) & 1);
        int rn = (jj >> 2) * 128 + wn * 32 + (jj & 3) * 8 + (lane & 7);
        bbase[pq] = (uint32_t)(rn * 64 + (((rn >> 1) & 3) << 4));
    }
    uint32_t aoff[2];
    {
        int row0 = ((lane >> 4) << 3) + (lane & 7);
        #pragma unroll
        for (int i = 0; i < 2; i++) {
            int col16 = ((wm * 32 + i * 16) >> 3) + ((lane >> 3) & 1);
            aoff[i] = (uint32_t)(row0 * 128 + ((col16 ^ (row0 & 7)) << 4));
        }
    }
    const uint32_t chlane = ((lane >> 3) & 1) << 4;

    // B chunk: [512 d][32 e] fp16 = 32KB; 3 stages, buffer = tc % 3
    #define B_PF(tc) do { \
        uint32_t bufo_ = (uint32_t)((tc) % 3) * 32768u; \
        _Pragma("unroll") \
        for (int q = 0; q < 8; q++) { \
            int idx = tid + q * 256; \
            int row = idx >> 2, c = idx & 3; \
            uint32_t dst = smB + bufo_ + row * 64 + \
                           (((uint32_t)(c ^ ((row >> 1) & 3))) << 4); \
            cp16(dst, (const char*)g_w1f + row * 1024 + (tc) * 64 + c * 16); \
        } \
        CP_COMMIT(); \
    } while (0)

    float4 st[2];
    #define A_LDG(kc) do { \
        _Pragma("unroll") \
        for (int q = 0; q < 2; q++) { \
            int idx = tid + q * 256; \
            int e = (kc) * 32 + (idx >> 4), c4 = idx & 15; \
            st[q] = __ldg((const float4*)(xA + (size_t)e * S_ + c4 * 4)); \
        } \
    } while (0)
    #define A_STS(kc) do { \
        _Pragma("unroll") \
        for (int q = 0; q < 2; q++) { \
            int idx = tid + q * 256; \
            int el = idx >> 4, c4 = idx & 15; \
            __half2 h01 = __floats2half2_rn(st[q].x, st[q].y); \
            __half2 h23 = __floats2half2_rn(st[q].z, st[q].w); \
            uint32_t off = (uint32_t)(((kc) & 1) * 4096 + el * 128 + \
                ((((c4 >> 1)) ^ (el & 7)) << 4) + (c4 & 1) * 8); \
            *(uint2*)(dsm + off) = make_uint2(h2u(h01), h2u(h23)); \
        } \
    } while (0)

    uint32_t C[2][16][2];
    #pragma unroll
    for (int i = 0; i < 2; i++)
        #pragma unroll
        for (int j = 0; j < 16; j++) { C[i][j][0] = 0u; C[i][j][1] = 0u; }

    B_PF(0);
    B_PF(1);
    A_LDG(0);
    A_STS(0);

    for (int t = 0; t < 16; ++t) {
        if (t < 15) A_LDG(t + 1);
        if (t >= 15) { CP_WAIT(0); } else { CP_WAIT(1); }
        __syncthreads();
        if (t + 2 < 16) B_PF(t + 2);   // writes buffer (t+2)%3 = (t-1)%3, just drained

        uint32_t Abase = smA + (t & 1) * 4096;
        uint32_t Bbase = smB + (uint32_t)(t % 3) * 32768u;
        #pragma unroll
        for (int kk = 0; kk < 2; kk++) {
            uint32_t a[2][4];
            ldsm4t(a[0], Abase + kk * 2048 + aoff[0]);
            ldsm4t(a[1], Abase + kk * 2048 + aoff[1]);
            uint32_t chx = chlane ^ ((uint32_t)kk << 5);
            #pragma unroll
            for (int pq = 0; pq < 8; pq++) {
                uint32_t bf[4];
                ldsm4(bf, Bbase + (bbase[pq] ^ chx));
                mma_h_h(C[0][2 * pq],     a[0], bf);
                mma_h_h(C[1][2 * pq],     a[1], bf);
                mma_h_h(C[0][2 * pq + 1], a[0], bf + 2);
                mma_h_h(C[1][2 * pq + 1], a[1], bf + 2);
            }
        }
        if (t < 15) A_STS(t + 1);
    }
    #undef B_PF
    #undef A_LDG
    #undef A_STS

    float acc[2][2] = {{0.f, 0.f}, {0.f, 0.f}};
    #pragma unroll
    for (int i = 0; i < 2; i++) {
        int r0 = wm * 32 + i * 16 + quad;
        #pragma unroll
        for (int j2 = 0; j2 < 16; j2++) {
            int d = (j2 >> 2) * 128 + wn * 32 + (j2 & 3) * 8 + qd * 2;
            float w2x = sW2[d], w2y = sW2[d + 1];
            float gx = sG[d],  gy = sG[d + 1];
            const float* p = g_p1 + (size_t)(s0 + r0) * D_ + d;
            float2 pA = *(const float2*)p;
            float2 pB = *(const float2*)(p + 8 * D_);
            __half2 ha = *(__half2*)&C[i][j2][0];
            __half2 hb = *(__half2*)&C[i][j2][1];
            float v0 = fmaxf(__low2float(ha)  + pA.x + gx, 0.f);
            float v1 = fmaxf(__high2float(ha) + pA.y + gy, 0.f);
            float v2 = fmaxf(__low2float(hb)  + pB.x + gx, 0.f);
            float v3 = fmaxf(__high2float(hb) + pB.y + gy, 0.f);
            acc[i][0] = fmaf(v0, w2x, fmaf(v1, w2y, acc[i][0]));
            acc[i][1] = fmaf(v2, w2x, fmaf(v3, w2y, acc[i][1]));
        }
    }

    #pragma unroll
    for (int i = 0; i < 2; i++)
        #pragma unroll
        for (int m = 0; m < 2; m++) {
            float v = acc[i][m];
            v += __shfl_xor_sync(0xffffffffu, v, 1);
            v += __shfl_xor_sync(0xffffffffu, v, 2);
            if (qd == 0) sred[wn][wm * 32 + i * 16 + m * 8 + quad] = v;
        }
    __syncthreads();
    if (tid < 64)
        g_score[(size_t)b * S_ + s0 + tid] =
            sred[0][tid] + sred[1][tid] + sred[2][tid] + sred[3][tid] + b2[0];
}

// ---------------------------------------------------------------
// 6) MERGED select: top-16 approx -> exact rescore -> top-8 ->
//    scatter ones + gather selected features (validated in R10).
// ---------------------------------------------------------------
__global__ void __launch_bounds__(512)
select_kernel(const float* __restrict__ x, const float* __restrict__ W2,
              float* __restrict__ out_idx, float* __restrict__ out_sel)
{
    __shared__ float xcol[NCAND][D_];
    __shared__ float cval[256];
    __shared__ int   cidx[256];
    __shared__ int   scand[NCAND];
    __shared__ float wsum[16][NCAND];
    __shared__ float cscore[NCAND];
    __shared__ int   chosen_s[K_];
    __shared__ int   cslot_s[K_];

    int b = blockIdx.x, tid = threadIdx.x;
    int w = tid >> 5, lane = tid & 31;
    const float* sc = g_score + (size_t)b * S_;

    float v[4];
    #pragma unroll
    for (int k = 0; k < 4; k++) v[k] = sc[w * 128 + k * 32 + lane];
    for (int it = 0; it < NCAND; it++) {
        float lv = v[0]; int lk = 0;
        #pragma unroll
        for (int k = 1; k < 4; k++)
            if (v[k] > lv) { lv = v[k]; lk = k; }
        int gidx = w * 128 + lk * 32 + lane;
        float bv = lv; int bi = gidx;
        #pragma unroll
        for (int off = 16; off > 0; off >>= 1) {
            float ov = __shfl_xor_sync(0xffffffffu, bv, off);
            int   oi = __shfl_xor_sync(0xffffffffu, bi, off);
            if (ov > bv || (ov == bv && oi < bi)) { bv = ov; bi = oi; }
        }
        if (gidx == bi) v[lk] = -INFINITY;
        if (lane == 0) { cval[w * 16 + it] = bv; cidx[w * 16 + it] = bi; }
    }
    __syncthreads();
    if (w == 0) {
        float v2[8]; int i2[8];
        #pragma unroll
        for (int k = 0; k < 8; k++) {
            v2[k] = cval[k * 32 + lane];
            i2[k] = cidx[k * 32 + lane];
        }
        for (int it = 0; it < NCAND; it++) {
            float lv = v2[0]; int lk = 0;
            #pragma unroll
            for (int k = 1; k < 8; k++)
                if (v2[k] > lv || (v2[k] == lv && i2[k] < i2[lk])) { lv = v2[k]; lk = k; }
            float bv = lv; int bi = i2[lk];
            #pragma unroll
            for (int off = 16; off > 0; off >>= 1) {
                float ov = __shfl_xor_sync(0xffffffffu, bv, off);
                int   oi = __shfl_xor_sync(0xffffffffu, bi, off);
                if (ov > bv || (ov == bv && oi < bi)) { bv = ov; bi = oi; }
            }
            if (i2[lk] == bi) v2[lk] = -INFINITY;
            if (lane == 0) scand[it] = bi;
        }
    }
    __syncthreads();

    for (int idx = tid; idx < NCAND * D_; idx += 512) {
        int c = idx >> 9, e = idx & 511;
        xcol[c][e] = x[((size_t)b * D_ + e) * S_ + scand[c]];
    }
    __syncthreads();

    int d = tid;
    float accv[NCAND];
    #pragma unroll
    for (int c = 0; c < NCAND; c++) accv[c] = 0.f;
    const float* wt = g_w1t + d;
    for (int e = 0; e < D_; e++) {
        float wv = wt[(size_t)e * D_];
        #pragma unroll
        for (int c = 0; c < NCAND; c++)
            accv[c] = fmaf(wv, xcol[c][e], accv[c]);
    }
    float w2v = W2[d];
    float gv  = g_gb[b * D_ + d];
    #pragma unroll
    for (int c = 0; c < NCAND; c++) {
        float hv = accv[c] + g_p1[(size_t)scand[c] * D_ + d] + gv;
        hv = fmaxf(hv, 0.f);
        float part = hv * w2v;
        #pragma unroll
        for (int off = 16; off > 0; off >>= 1)
            part += __shfl_xor_sync(0xffffffffu, part, off);
        if (lane == 0) wsum[w][c] = part;
    }
    __syncthreads();
    if (tid < NCAND) {
        float s = 0.f;
        #pragma unroll
        for (int q = 0; q < 16; q++) s += wsum[q][tid];
        cscore[tid] = s;
    }
    __syncthreads();

    if (tid == 0) {
        bool used[NCAND];
        #pragma unroll
        for (int c = 0; c < NCAND; c++) used[c] = false;
        int ch[K_], sl[K_];
        for (int k = 0; k < K_; k++) {
            float best = -INFINITY; int bi = S_, bc = -1;
            for (int c = 0; c < NCAND; c++) {
                if (used[c]) continue;
                if (cscore[c] > best || (cscore[c] == best && scand[c] < bi)) {
                    best = cscore[c]; bi = scand[c]; bc = c;
                }
            }
            used[bc] = true;
            ch[k] = bi; sl[k] = bc;
        }
        for (int a = 1; a < K_; a++) {
            int vv = ch[a], ss = sl[a]; int j = a - 1;
            while (j >= 0 && ch[j] > vv) {
                ch[j + 1] = ch[j]; sl[j + 1] = sl[j]; j--;
            }
            ch[j + 1] = vv; sl[j + 1] = ss;
        }
        for (int k = 0; k < K_; k++) { chosen_s[k] = ch[k]; cslot_s[k] = sl[k]; }
    }
    __syncthreads();

    if (tid < K_)
        out_idx[((size_t)b * K_ + tid) * S_ + chosen_s[tid]] = 1.0f;
    #pragma unroll
    for (int k = 0; k < K_; k++)
        out_sel[((size_t)b * K_ + k) * D_ + tid] = xcol[cslot_s[k]][tid];
}

// ---------------------------------------------------------------
// 7) zero indices output
// ---------------------------------------------------------------
__global__ void zero_indices_kernel(float* __restrict__ out) {
    size_t i = (size_t)blockIdx.x * blockDim.x + threadIdx.x;
    ((float4*)out)[i] = make_float4(0.f, 0.f, 0.f, 0.f);
}

// ---------------------------------------------------------------
extern "C" void kernel_launch(void* const* d_in, const int* in_sizes, int n_in,
                              void* d_out, int out_size) {
    const float* x  = (const float*)d_in[0];
    const float* W1 = (const float*)d_in[1];
    const float* b1 = (const float*)d_in[2];
    const float* W2 = (const float*)d_in[3];
    const float* b2 = (const float*)d_in[4];
    float* out = (float*)d_out;

    const size_t IDX_SZ = (size_t)B_ * K_ * S_;
    const size_t SEL_SZ = (size_t)B_ * K_ * D_;
    float* out_idx  = out;
    float* out_sel  = out + IDX_SZ;
    float* out_feat = out + IDX_SZ + SEL_SZ;

    static cudaStream_t s1 = nullptr;
    static cudaEvent_t evFork = nullptr, evJoin = nullptr;
    if (s1 == nullptr) {
        cudaStreamCreateWithFlags(&s1, cudaStreamNonBlocking);
        cudaEventCreateWithFlags(&evFork, cudaEventDisableTiming);
        cudaEventCreateWithFlags(&evJoin, cudaEventDisableTiming);
        cudaFuncSetAttribute(fused_mma_kernel,
                             cudaFuncAttributeMaxDynamicSharedMemorySize, SMEM_DYN);
        cudaFuncSetAttribute(p1_mma_kernel,
                             cudaFuncAttributeMaxDynamicSharedMemorySize, P1_SMEM);
    }

    // fork: transpose + zero on s1 (independent of PE/W1/p1 chain)
    cudaEventRecord(evFork, 0);
    cudaStreamWaitEvent(s1, evFork, 0);
    transpose_fused_kernel<<<dim3(S_ / 32, D_ / 32, B_), dim3(32, 8), 0, s1>>>(x, out_feat);
    zero_indices_kernel<<<(unsigned)(IDX_SZ / 4 / 256), 256, 0, s1>>>(out_idx);
    cudaEventRecord(evJoin, s1);

    // main: pew1 + p1 run concurrently with the transpose
    pew1_kernel<<<S_ + (D_ * TWO_D) / 512, 512>>>(W1);
    p1_mma_kernel<<<dim3(S_ / 64, D_ / 64), 256, P1_SMEM>>>(b1);

    // join, then dependent chain
    cudaStreamWaitEvent(0, evJoin, 0);
    meang_kernel<<<B_, 512>>>(W1);
    fused_mma_kernel<<<dim3(S_ / 64, B_), 256, SMEM_DYN>>>(x, W2, b2);
    select_kernel<<<B_, 512>>>(x, W2, out_idx, out_sel);
}

// round 12
// speedup vs baseline: 1.1376x; 1.1115x over previous
#include <cuda_runtime.h>
#include <cuda_bf16.h>
#include <cuda_fp16.h>
#include <math.h>
#include <stdint.h>

#define B_    64
#define D_    512
#define S_    2048
#define K_    8
#define NCAND 16
#define TWO_D 1024

// ---------------- scratch (static device globals) ----------------
__device__ __nv_bfloat16 g_pehi[S_ * TWO_D];   // PE hi [s][e]
__device__ __nv_bfloat16 g_pelo[S_ * TWO_D];   // PE lo [s][e]
__device__ __nv_bfloat16 g_w1h [D_ * TWO_D];   // W1 hi [d][e] full
__device__ __nv_bfloat16 g_w1lo[D_ * TWO_D];   // W1 lo [d][e] full
__device__ __half        g_w1f [D_ * D_];      // W1[:, :512] fp16 [d][e]
__device__ float g_w1t [D_ * D_];              // W1[:, :512] fp32 [e][d]
__device__ float g_p1  [S_ * D_];              // PE@W1^T + b1 [s][d]
__device__ float g_mpart[(S_ / 32) * B_ * D_]; // mean partials [tile][b*D+d]
__device__ float g_gb  [B_ * D_];
__device__ float g_score[B_ * S_];

// ---------------- PTX helpers ----------------
__device__ __forceinline__ uint32_t smem_u32(const void* p) {
    return (uint32_t)__cvta_generic_to_shared(p);
}
__device__ __forceinline__ uint32_t h2u(__half2 h) {
    union { __half2 h; uint32_t u; } cvt;
    cvt.h = h;
    return cvt.u;
}
__device__ __forceinline__ void cp16(uint32_t dst, const void* src) {
    asm volatile("cp.async.cg.shared.global [%0], [%1], 16;" :: "r"(dst), "l"(src));
}
#define CP_COMMIT() asm volatile("cp.async.commit_group;" ::: "memory")
#define CP_WAIT(n)  asm volatile("cp.async.wait_group %0;" :: "n"(n) : "memory")

__device__ __forceinline__ void ldsm4(uint32_t* r, uint32_t a) {
    asm volatile("ldmatrix.sync.aligned.m8n8.x4.shared.b16 {%0,%1,%2,%3}, [%4];"
        : "=r"(r[0]), "=r"(r[1]), "=r"(r[2]), "=r"(r[3]) : "r"(a));
}
__device__ __forceinline__ void ldsm4t(uint32_t* r, uint32_t a) {
    asm volatile("ldmatrix.sync.aligned.m8n8.x4.trans.shared.b16 {%0,%1,%2,%3}, [%4];"
        : "=r"(r[0]), "=r"(r[1]), "=r"(r[2]), "=r"(r[3]) : "r"(a));
}
__device__ __forceinline__ void ldsm2(uint32_t* r, uint32_t a) {
    asm volatile("ldmatrix.sync.aligned.m8n8.x2.shared.b16 {%0,%1}, [%2];"
        : "=r"(r[0]), "=r"(r[1]) : "r"(a));
}
__device__ __forceinline__ void mma_bf_f32(float* c, const uint32_t* a, const uint32_t* b) {
    asm volatile(
        "mma.sync.aligned.m16n8k16.row.col.f32.bf16.bf16.f32 "
        "{%0,%1,%2,%3}, {%4,%5,%6,%7}, {%8,%9}, {%0,%1,%2,%3};"
        : "+f"(c[0]), "+f"(c[1]), "+f"(c[2]), "+f"(c[3])
        : "r"(a[0]), "r"(a[1]), "r"(a[2]), "r"(a[3]), "r"(b[0]), "r"(b[1]));
}
__device__ __forceinline__ void mma_h_h(uint32_t* c, const uint32_t* a, const uint32_t* b) {
    asm volatile(
        "mma.sync.aligned.m16n8k16.row.col.f16.f16.f16.f16 "
        "{%0,%1}, {%2,%3,%4,%5}, {%6,%7}, {%0,%1};"
        : "+r"(c[0]), "+r"(c[1])
        : "r"(a[0]), "r"(a[1]), "r"(a[2]), "r"(a[3]), "r"(b[0]), "r"(b[1]));
}

// ---------------------------------------------------------------
// 1) transpose (32x32): x[b][d][s] -> out_feat[b][s][d] + mean partials
// ---------------------------------------------------------------
__global__ void transpose_fused_kernel(const float* __restrict__ x,
                                       float* __restrict__ out_feat) {
    __shared__ float tile[32][33];
    int b  = blockIdx.z;
    int d0 = blockIdx.y * 32;
    int s0 = blockIdx.x * 32;
    const float* xb = x + (size_t)b * D_ * S_;
    #pragma unroll
    for (int r = 0; r < 32; r += 8)
        tile[threadIdx.y + r][threadIdx.x] =
            xb[(size_t)(d0 + threadIdx.y + r) * S_ + s0 + threadIdx.x];
    __syncthreads();
    float* ob = out_feat + (size_t)b * S_ * D_;
    #pragma unroll
    for (int r = 0; r < 32; r += 8) {
        int s = s0 + threadIdx.y + r;
        ob[(size_t)s * D_ + d0 + threadIdx.x] = tile[threadIdx.x][threadIdx.y + r];
    }
    if (threadIdx.y == 0) {
        float sum = 0.f;
        #pragma unroll
        for (int sl = 0; sl < 32; sl++) sum += tile[threadIdx.x][sl];
        g_mpart[(size_t)blockIdx.x * (B_ * D_) + b * D_ + d0 + threadIdx.x] = sum;
    }
}

// ---------------------------------------------------------------
// 2) PE (hi/lo bf16) + W1 conversions
// ---------------------------------------------------------------
__global__ void pew1_kernel(const float* __restrict__ W1) {
    int bx = blockIdx.x;
    if (bx < S_) {
        int s = bx, i = threadIdx.x;
        float div = expf(-(float)(2 * i) * (logf(10000.0f) / (float)TWO_D));
        float sv, cv;
        sincosf((float)s * div, &sv, &cv);
        __nv_bfloat16 hs = __float2bfloat16_rn(sv);
        __nv_bfloat16 hc = __float2bfloat16_rn(cv);
        __nv_bfloat16 ls = __float2bfloat16_rn(sv - __bfloat162float(hs));
        __nv_bfloat16 lc = __float2bfloat16_rn(cv - __bfloat162float(hc));
        ((__nv_bfloat162*)g_pehi)[(size_t)s * (TWO_D / 2) + i] =
            __nv_bfloat162(hs, hc);
        ((__nv_bfloat162*)g_pelo)[(size_t)s * (TWO_D / 2) + i] =
            __nv_bfloat162(ls, lc);
    } else {
        int idx = (bx - S_) * 512 + threadIdx.x;
        int d = idx >> 10, e = idx & 1023;
        float v = W1[idx];
        __nv_bfloat16 h = __float2bfloat16_rn(v);
        g_w1h[idx]  = h;
        g_w1lo[idx] = __float2bfloat16_rn(v - __bfloat162float(h));
        if (e < 512) {
            g_w1f[d * 512 + e] = __float2half_rn(v);
            g_w1t[(size_t)e * D_ + d] = v;
        }
    }
}

// ---------------------------------------------------------------
// 3) meang (runs on s1, overlaps p1): mean + g = mean . W1[:,512:]
// ---------------------------------------------------------------
__global__ void meang_kernel(const float* __restrict__ W1) {
    __shared__ float sm[D_];
    int b = blockIdx.x, d = threadIdx.x;
    float s = 0.f;
    #pragma unroll
    for (int t = 0; t < S_ / 32; t++)
        s += g_mpart[(size_t)t * (B_ * D_) + b * D_ + d];
    sm[d] = s * (1.0f / S_);
    __syncthreads();
    const float4* w = (const float4*)(W1 + (size_t)d * TWO_D + D_);
    float acc = 0.f;
    #pragma unroll 8
    for (int e4 = 0; e4 < D_ / 4; e4++) {
        float4 v = w[e4];
        acc = fmaf(sm[4 * e4 + 0], v.x, acc);
        acc = fmaf(sm[4 * e4 + 1], v.y, acc);
        acc = fmaf(sm[4 * e4 + 2], v.z, acc);
        acc = fmaf(sm[4 * e4 + 3], v.w, acc);
    }
    g_gb[b * D_ + d] = acc;
}

// ---------------------------------------------------------------
// 4) p1 via hi/lo bf16 MMA, 64x64 tiles -> 256 CTAs
// ---------------------------------------------------------------
#define P1_SMEM (2 * 32768)

__global__ void __launch_bounds__(256, 1)
p1_mma_kernel(const float* __restrict__ b1) {
    extern __shared__ char dsm[];
    uint32_t smb = smem_u32(dsm);
    int tid = threadIdx.x, lane = tid & 31, w = tid >> 5;
    int wm = w & 1, wn = w >> 1;
    int quad = lane >> 2, qd = lane & 3;
    int s0 = blockIdx.x * 64;
    int d0b = blockIdx.y * 64;

    const char* Ah = (const char*)g_pehi + (size_t)s0 * 2048;
    const char* Al = (const char*)g_pelo + (size_t)s0 * 2048;
    const char* Bh = (const char*)g_w1h + (size_t)d0b * 2048;
    const char* Bl = (const char*)g_w1lo + (size_t)d0b * 2048;

    #define P1_PF(t) do { \
        uint32_t base_ = smb + ((t) & 1) * 32768; \
        _Pragma("unroll") \
        for (int q = 0; q < 2; q++) { \
            int idx = tid + q * 256; \
            int row = idx >> 3, c = idx & 7; \
            uint32_t off = row * 128 + (((c ^ (row & 7))) << 4); \
            size_t src = (size_t)row * 2048 + (size_t)(t) * 128 + c * 16; \
            cp16(base_ + off,          Ah + src); \
            cp16(base_ + 8192 + off,   Al + src); \
            cp16(base_ + 16384 + off,  Bh + src); \
            cp16(base_ + 24576 + off,  Bl + src); \
        } \
        CP_COMMIT(); \
    } while (0)

    P1_PF(0);
    P1_PF(1);

    float C[2][2][4];
    #pragma unroll
    for (int i = 0; i < 2; i++)
        #pragma unroll
        for (int j = 0; j < 2; j++)
            #pragma unroll
            for (int k = 0; k < 4; k++) C[i][j][k] = 0.f;

    for (int t = 0; t < 16; ++t) {
        if (t >= 14) { CP_WAIT(0); } else { CP_WAIT(1); }
        __syncthreads();
        uint32_t bA = smb + (t & 1) * 32768;
        #pragma unroll
        for (int kk = 0; kk < 4; kk++) {
            uint32_t ah[2][4], al[2][4];
            #pragma unroll
            for (int i = 0; i < 2; i++) {
                int r = wm * 32 + i * 16 + (lane & 15);
                uint32_t ch = (uint32_t)((kk << 1) | (lane >> 4));
                uint32_t off = r * 128 + ((ch ^ (uint32_t)(r & 7)) << 4);
                ldsm4(ah[i], bA + off);
                ldsm4(al[i], bA + 8192 + off);
            }
            uint32_t bh[2][2], bl[2][2];
            #pragma unroll
            for (int j = 0; j < 2; j++) {
                int rn = wn * 16 + j * 8 + (lane & 7);
                uint32_t ch = (uint32_t)((kk << 1) | ((lane >> 3) & 1));
                uint32_t off = rn * 128 + ((ch ^ (uint32_t)(rn & 7)) << 4);
                ldsm2(bh[j], bA + 16384 + off);
                ldsm2(bl[j], bA + 24576 + off);
            }
            #pragma unroll
            for (int i = 0; i < 2; i++)
                #pragma unroll
                for (int j = 0; j < 2; j++) {
                    mma_bf_f32(C[i][j], ah[i], bh[j]);
                    mma_bf_f32(C[i][j], ah[i], bl[j]);
                    mma_bf_f32(C[i][j], al[i], bh[j]);
                }
        }
        __syncthreads();
        if (t + 2 < 16) P1_PF(t + 2);
    }

    #pragma unroll
    for (int i = 0; i < 2; i++) {
        int sg = s0 + wm * 32 + i * 16 + quad;
        #pragma unroll
        for (int j = 0; j < 2; j++) {
            int d = d0b + wn * 16 + j * 8 + qd * 2;
            float2 bv = *(const float2*)(b1 + d);
            *(float2*)(g_p1 + (size_t)sg * D_ + d) =
                make_float2(C[i][j][0] + bv.x, C[i][j][1] + bv.y);
            *(float2*)(g_p1 + (size_t)(sg + 8) * D_ + d) =
                make_float2(C[i][j][2] + bv.x, C[i][j][3] + bv.y);
        }
    }
    #undef P1_PF
}

// ---------------------------------------------------------------
// 5) MAIN v4 (R9/R10 measured config): fp16 mma (f16 accum),
//    s-tile 64, nb-inner, 2-stage B, precomputed swizzle addrs.
// ---------------------------------------------------------------
#define SMEM_A    (2 * 4096)
#define SMEM_Boff SMEM_A
#define SMEM_DYN  (SMEM_A + 2 * 32768)  // 72KB -> 2 CTAs/SM

__global__ void __launch_bounds__(256, 2)
fused_mma_kernel(const float* __restrict__ x, const float* __restrict__ W2,
                 const float* __restrict__ b2)
{
    extern __shared__ char dsm[];
    __shared__ float sW2[D_];
    __shared__ float sG[D_];
    __shared__ float sred[4][64];

    const uint32_t smA = smem_u32(dsm);
    const uint32_t smB = smA + SMEM_Boff;

    int tid = threadIdx.x;
    int lane = tid & 31;
    int w = tid >> 5;
    int wm = w & 1, wn = w >> 1;
    int quad = lane >> 2, qd = lane & 3;
    int b = blockIdx.y;
    int s0 = blockIdx.x * 64;

    for (int i = tid; i < D_; i += 256) {
        sW2[i] = W2[i];
        sG[i]  = g_gb[b * D_ + i];
    }

    const float* xA = x + (size_t)b * D_ * S_ + s0;

    uint32_t bbase[8];
    #pragma unroll
    for (int pq = 0; pq < 8; pq++) {
        int jj = 2 * pq + ((lane >> 4) & 1);
        int rn = (jj >> 2) * 128 + wn * 32 + (jj & 3) * 8 + (lane & 7);
        bbase[pq] = (uint32_t)(rn * 64 + (((rn >> 1) & 3) << 4));
    }
    uint32_t aoff[2];
    {
        int row0 = ((lane >> 4) << 3) + (lane & 7);
        #pragma unroll
        for (int i = 0; i < 2; i++) {
            int col16 = ((wm * 32 + i * 16) >> 3) + ((lane >> 3) & 1);
            aoff[i] = (uint32_t)(row0 * 128 + ((col16 ^ (row0 & 7)) << 4));
        }
    }
    const uint32_t chlane = ((lane >> 3) & 1) << 4;

    #define B_PF(tc) do { \
        _Pragma("unroll") \
        for (int q = 0; q < 8; q++) { \
            int idx = tid + q * 256; \
            int row = idx >> 2, c = idx & 3; \
            uint32_t dst = smB + ((tc) & 1) * 32768 + row * 64 + \
                           (((uint32_t)(c ^ ((row >> 1) & 3))) << 4); \
            cp16(dst, (const char*)g_w1f + row * 1024 + (tc) * 64 + c * 16); \
        } \
        CP_COMMIT(); \
    } while (0)

    float4 st[2];
    #define A_LDG(kc) do { \
        _Pragma("unroll") \
        for (int q = 0; q < 2; q++) { \
            int idx = tid + q * 256; \
            int e = (kc) * 32 + (idx >> 4), c4 = idx & 15; \
            st[q] = __ldg((const float4*)(xA + (size_t)e * S_ + c4 * 4)); \
        } \
    } while (0)
    #define A_STS(kc) do { \
        _Pragma("unroll") \
        for (int q = 0; q < 2; q++) { \
            int idx = tid + q * 256; \
            int el = idx >> 4, c4 = idx & 15; \
            __half2 h01 = __floats2half2_rn(st[q].x, st[q].y); \
            __half2 h23 = __floats2half2_rn(st[q].z, st[q].w); \
            uint32_t off = (uint32_t)(((kc) & 1) * 4096 + el * 128 + \
                ((((c4 >> 1)) ^ (el & 7)) << 4) + (c4 & 1) * 8); \
            *(uint2*)(dsm + off) = make_uint2(h2u(h01), h2u(h23)); \
        } \
    } while (0)

    uint32_t C[2][16][2];
    #pragma unroll
    for (int i = 0; i < 2; i++)
        #pragma unroll
        for (int j = 0; j < 16; j++) { C[i][j][0] = 0u; C[i][j][1] = 0u; }

    B_PF(0);
    A_LDG(0);
    A_STS(0);

    for (int t = 0; t < 16; ++t) {
        if (t < 15) A_LDG(t + 1);
        if (t < 15) B_PF(t + 1);
        if (t >= 15) { CP_WAIT(0); } else { CP_WAIT(1); }
        __syncthreads();

        uint32_t Abase = smA + (t & 1) * 4096;
        uint32_t Bbase = smB + (t & 1) * 32768;
        #pragma unroll
        for (int kk = 0; kk < 2; kk++) {
            uint32_t a[2][4];
            ldsm4t(a[0], Abase + kk * 2048 + aoff[0]);
            ldsm4t(a[1], Abase + kk * 2048 + aoff[1]);
            uint32_t chx = chlane ^ ((uint32_t)kk << 5);
            #pragma unroll
            for (int pq = 0; pq < 8; pq++) {
                uint32_t bf[4];
                ldsm4(bf, Bbase + (bbase[pq] ^ chx));
                mma_h_h(C[0][2 * pq],     a[0], bf);
                mma_h_h(C[1][2 * pq],     a[1], bf);
                mma_h_h(C[0][2 * pq + 1], a[0], bf + 2);
                mma_h_h(C[1][2 * pq + 1], a[1], bf + 2);
            }
        }
        if (t < 15) A_STS(t + 1);
    }
    #undef B_PF
    #undef A_LDG
    #undef A_STS

    float acc[2][2] = {{0.f, 0.f}, {0.f, 0.f}};
    #pragma unroll
    for (int i = 0; i < 2; i++) {
        int r0 = wm * 32 + i * 16 + quad;
        #pragma unroll
        for (int j2 = 0; j2 < 16; j2++) {
            int d = (j2 >> 2) * 128 + wn * 32 + (j2 & 3) * 8 + qd * 2;
            float w2x = sW2[d], w2y = sW2[d + 1];
            float gx = sG[d],  gy = sG[d + 1];
            const float* p = g_p1 + (size_t)(s0 + r0) * D_ + d;
            float2 pA = *(const float2*)p;
            float2 pB = *(const float2*)(p + 8 * D_);
            __half2 ha = *(__half2*)&C[i][j2][0];
            __half2 hb = *(__half2*)&C[i][j2][1];
            float v0 = fmaxf(__low2float(ha)  + pA.x + gx, 0.f);
            float v1 = fmaxf(__high2float(ha) + pA.y + gy, 0.f);
            float v2 = fmaxf(__low2float(hb)  + pB.x + gx, 0.f);
            float v3 = fmaxf(__high2float(hb) + pB.y + gy, 0.f);
            acc[i][0] = fmaf(v0, w2x, fmaf(v1, w2y, acc[i][0]));
            acc[i][1] = fmaf(v2, w2x, fmaf(v3, w2y, acc[i][1]));
        }
    }

    #pragma unroll
    for (int i = 0; i < 2; i++)
        #pragma unroll
        for (int m = 0; m < 2; m++) {
            float v = acc[i][m];
            v += __shfl_xor_sync(0xffffffffu, v, 1);
            v += __shfl_xor_sync(0xffffffffu, v, 2);
            if (qd == 0) sred[wn][wm * 32 + i * 16 + m * 8 + quad] = v;
        }
    __syncthreads();
    if (tid < 64)
        g_score[(size_t)b * S_ + s0 + tid] =
            sred[0][tid] + sred[1][tid] + sred[2][tid] + sred[3][tid] + b2[0];
}

// ---------------------------------------------------------------
// 6) MERGED select (R10-validated): top-16 -> exact rescore ->
//    top-8 -> scatter ones + gather selected features from smem.
// ---------------------------------------------------------------
__global__ void __launch_bounds__(512)
select_kernel(const float* __restrict__ x, const float* __restrict__ W2,
              float* __restrict__ out_idx, float* __restrict__ out_sel)
{
    __shared__ float xcol[NCAND][D_];
    __shared__ float cval[256];
    __shared__ int   cidx[256];
    __shared__ int   scand[NCAND];
    __shared__ float wsum[16][NCAND];
    __shared__ float cscore[NCAND];
    __shared__ int   chosen_s[K_];
    __shared__ int   cslot_s[K_];

    int b = blockIdx.x, tid = threadIdx.x;
    int w = tid >> 5, lane = tid & 31;
    const float* sc = g_score + (size_t)b * S_;

    float v[4];
    #pragma unroll
    for (int k = 0; k < 4; k++) v[k] = sc[w * 128 + k * 32 + lane];
    for (int it = 0; it < NCAND; it++) {
        float lv = v[0]; int lk = 0;
        #pragma unroll
        for (int k = 1; k < 4; k++)
            if (v[k] > lv) { lv = v[k]; lk = k; }
        int gidx = w * 128 + lk * 32 + lane;
        float bv = lv; int bi = gidx;
        #pragma unroll
        for (int off = 16; off > 0; off >>= 1) {
            float ov = __shfl_xor_sync(0xffffffffu, bv, off);
            int   oi = __shfl_xor_sync(0xffffffffu, bi, off);
            if (ov > bv || (ov == bv && oi < bi)) { bv = ov; bi = oi; }
        }
        if (gidx == bi) v[lk] = -INFINITY;
        if (lane == 0) { cval[w * 16 + it] = bv; cidx[w * 16 + it] = bi; }
    }
    __syncthreads();
    if (w == 0) {
        float v2[8]; int i2[8];
        #pragma unroll
        for (int k = 0; k < 8; k++) {
            v2[k] = cval[k * 32 + lane];
            i2[k] = cidx[k * 32 + lane];
        }
        for (int it = 0; it < NCAND; it++) {
            float lv = v2[0]; int lk = 0;
            #pragma unroll
            for (int k = 1; k < 8; k++)
                if (v2[k] > lv || (v2[k] == lv && i2[k] < i2[lk])) { lv = v2[k]; lk = k; }
            float bv = lv; int bi = i2[lk];
            #pragma unroll
            for (int off = 16; off > 0; off >>= 1) {
                float ov = __shfl_xor_sync(0xffffffffu, bv, off);
                int   oi = __shfl_xor_sync(0xffffffffu, bi, off);
                if (ov > bv || (ov == bv && oi < bi)) { bv = ov; bi = oi; }
            }
            if (i2[lk] == bi) v2[lk] = -INFINITY;
            if (lane == 0) scand[it] = bi;
        }
    }
    __syncthreads();

    for (int idx = tid; idx < NCAND * D_; idx += 512) {
        int c = idx >> 9, e = idx & 511;
        xcol[c][e] = x[((size_t)b * D_ + e) * S_ + scand[c]];
    }
    __syncthreads();

    int d = tid;
    float accv[NCAND];
    #pragma unroll
    for (int c = 0; c < NCAND; c++) accv[c] = 0.f;
    const float* wt = g_w1t + d;
    for (int e = 0; e < D_; e++) {
        float wv = wt[(size_t)e * D_];
        #pragma unroll
        for (int c = 0; c < NCAND; c++)
            accv[c] = fmaf(wv, xcol[c][e], accv[c]);
    }
    float w2v = W2[d];
    float gv  = g_gb[b * D_ + d];
    #pragma unroll
    for (int c = 0; c < NCAND; c++) {
        float hv = accv[c] + g_p1[(size_t)scand[c] * D_ + d] + gv;
        hv = fmaxf(hv, 0.f);
        float part = hv * w2v;
        #pragma unroll
        for (int off = 16; off > 0; off >>= 1)
            part += __shfl_xor_sync(0xffffffffu, part, off);
        if (lane == 0) wsum[w][c] = part;
    }
    __syncthreads();
    if (tid < NCAND) {
        float s = 0.f;
        #pragma unroll
        for (int q = 0; q < 16; q++) s += wsum[q][tid];
        cscore[tid] = s;
    }
    __syncthreads();

    if (tid == 0) {
        bool used[NCAND];
        #pragma unroll
        for (int c = 0; c < NCAND; c++) used[c] = false;
        int ch[K_], sl[K_];
        for (int k = 0; k < K_; k++) {
            float best = -INFINITY; int bi = S_, bc = -1;
            for (int c = 0; c < NCAND; c++) {
                if (used[c]) continue;
                if (cscore[c] > best || (cscore[c] == best && scand[c] < bi)) {
                    best = cscore[c]; bi = scand[c]; bc = c;
                }
            }
            used[bc] = true;
            ch[k] = bi; sl[k] = bc;
        }
        for (int a = 1; a < K_; a++) {
            int vv = ch[a], ss = sl[a]; int j = a - 1;
            while (j >= 0 && ch[j] > vv) {
                ch[j + 1] = ch[j]; sl[j + 1] = sl[j]; j--;
            }
            ch[j + 1] = vv; sl[j + 1] = ss;
        }
        for (int k = 0; k < K_; k++) { chosen_s[k] = ch[k]; cslot_s[k] = sl[k]; }
    }
    __syncthreads();

    if (tid < K_)
        out_idx[((size_t)b * K_ + tid) * S_ + chosen_s[tid]] = 1.0f;
    #pragma unroll
    for (int k = 0; k < K_; k++)
        out_sel[((size_t)b * K_ + k) * D_ + tid] = xcol[cslot_s[k]][tid];
}

// ---------------------------------------------------------------
// 7) zero indices output
// ---------------------------------------------------------------
__global__ void zero_indices_kernel(float* __restrict__ out) {
    size_t i = (size_t)blockIdx.x * blockDim.x + threadIdx.x;
    ((float4*)out)[i] = make_float4(0.f, 0.f, 0.f, 0.f);
}

// ---------------------------------------------------------------
extern "C" void kernel_launch(void* const* d_in, const int* in_sizes, int n_in,
                              void* d_out, int out_size) {
    const float* x  = (const float*)d_in[0];
    const float* W1 = (const float*)d_in[1];
    const float* b1 = (const float*)d_in[2];
    const float* W2 = (const float*)d_in[3];
    const float* b2 = (const float*)d_in[4];
    float* out = (float*)d_out;

    const size_t IDX_SZ = (size_t)B_ * K_ * S_;
    const size_t SEL_SZ = (size_t)B_ * K_ * D_;
    float* out_idx  = out;
    float* out_sel  = out + IDX_SZ;
    float* out_feat = out + IDX_SZ + SEL_SZ;

    static cudaStream_t s1 = nullptr;
    static cudaEvent_t evFork = nullptr, evJoin = nullptr;
    if (s1 == nullptr) {
        cudaStreamCreateWithFlags(&s1, cudaStreamNonBlocking);
        cudaEventCreateWithFlags(&evFork, cudaEventDisableTiming);
        cudaEventCreateWithFlags(&evJoin, cudaEventDisableTiming);
        cudaFuncSetAttribute(fused_mma_kernel,
                             cudaFuncAttributeMaxDynamicSharedMemorySize, SMEM_DYN);
        cudaFuncSetAttribute(p1_mma_kernel,
                             cudaFuncAttributeMaxDynamicSharedMemorySize, P1_SMEM);
    }

    // fork: transpose -> zero -> meang on s1 (independent of pew1/p1 chain)
    cudaEventRecord(evFork, 0);
    cudaStreamWaitEvent(s1, evFork, 0);
    transpose_fused_kernel<<<dim3(S_ / 32, D_ / 32, B_), dim3(32, 8), 0, s1>>>(x, out_feat); // 1
    zero_indices_kernel<<<(unsigned)(IDX_SZ / 4 / 256), 256, 0, s1>>>(out_idx);              // 2
    meang_kernel<<<B_, 512, 0, s1>>>(W1);                                                    // 3
    cudaEventRecord(evJoin, s1);

    // main: pew1 + p1 run concurrently with the s1 chain
    pew1_kernel<<<S_ + (D_ * TWO_D) / 512, 512>>>(W1);                                       // 4 (profiled)
    p1_mma_kernel<<<dim3(S_ / 64, D_ / 64), 256, P1_SMEM>>>(b1);                             // 5

    // join, then dependent chain
    cudaStreamWaitEvent(0, evJoin, 0);
    fused_mma_kernel<<<dim3(S_ / 64, B_), 256, SMEM_DYN>>>(x, W2, b2);                       // 6
    select_kernel<<<B_, 512>>>(x, W2, out_idx, out_sel);                                     // 7
}